// round 1
// baseline (speedup 1.0000x reference)
#include <cuda_runtime.h>
#include <math_constants.h>

// ---------------------------------------------------------------------------
// IttiKochSaliency on x[8,3,512,512] f32 -> out[8,512,512] f32
//
// Pipeline (all scratch in __device__ globals, no allocation):
//  k_init      : reset min/max encodings + tile sums
//  k_minmax    : per-(b,c) min/max of x (atomic, order-preserving uint encode)
//  k_pyrdown x8: separable 6-tap [1,5,10,10,5,1]/32 stride-2 reflect filter
//                (== 5x5 binomial conv + bilinear half resize). Level 1 fuses
//                the per-channel input normalization.
//  k_diff  x7  : d_i = |pyr[i+1] - nearest_up(pyr[i+2])|, per-(b,c,i) min/max
//                atomics, and 16x16 tile-max sums (block == tile).
//  k_scale     : turn (mn,mx,tilesum) into per-(b,c,i) affine (s, off);
//                off collapses to a per-b constant.
//  k_final     : one fused gather: for each of 8*512^2 output pixels,
//                bilinear-sample all 7 levels x 3 channels, scale, mean.
// ---------------------------------------------------------------------------

#define BC 24  // 8 batches * 3 channels

// pyramid levels 1..8 stored as k=0..7, sizes (256>>k)^2 per (b,c)
__device__ float g_pyr[2097120];
// diff maps i=0..6, sizes (256>>i)^2 per (b,c)
__device__ float g_d[2097024];
__device__ unsigned g_xmn[BC], g_xmx[BC];
__device__ unsigned g_dmn[BC * 7], g_dmx[BC * 7];
__device__ float g_tsum[BC * 7];
__device__ float g_s[BC * 7];
__device__ float g_offtot[8];

// float offsets of stored level k (levels are [BC][h][h], h = 256>>k)
__constant__ int c_off[8] = {0, 1572864, 1966080, 2064384,
                             2088960, 2095104, 2096640, 2097024};

__device__ __forceinline__ unsigned fenc(float f) {
    unsigned u = __float_as_uint(f);
    return (u & 0x80000000u) ? ~u : (u | 0x80000000u);
}
__device__ __forceinline__ float fdec(unsigned u) {
    return __uint_as_float((u & 0x80000000u) ? (u ^ 0x80000000u) : ~u);
}

__global__ void k_init() {
    int t = threadIdx.x;
    if (t < BC) { g_xmn[t] = 0xFFFFFFFFu; g_xmx[t] = 0u; }
    if (t < BC * 7) { g_dmn[t] = 0xFFFFFFFFu; g_dmx[t] = 0u; g_tsum[t] = 0.f; }
}

// grid (24, 16), block 256: per-channel min/max via float4 scan + atomics
__global__ void k_minmax(const float* __restrict__ x) {
    int bc = blockIdx.x;
    const float4* p4 = (const float4*)(x + (size_t)bc * 262144 + blockIdx.y * 16384);
    float mn = CUDART_INF_F, mx = -CUDART_INF_F;
    for (int i = threadIdx.x; i < 4096; i += 256) {
        float4 v = p4[i];
        mn = fminf(mn, fminf(fminf(v.x, v.y), fminf(v.z, v.w)));
        mx = fmaxf(mx, fmaxf(fmaxf(v.x, v.y), fmaxf(v.z, v.w)));
    }
    for (int o = 16; o; o >>= 1) {
        mn = fminf(mn, __shfl_xor_sync(~0u, mn, o));
        mx = fmaxf(mx, __shfl_xor_sync(~0u, mx, o));
    }
    __shared__ float smn[8], smx[8];
    if ((threadIdx.x & 31) == 0) { smn[threadIdx.x >> 5] = mn; smx[threadIdx.x >> 5] = mx; }
    __syncthreads();
    if (threadIdx.x == 0) {
        for (int w = 1; w < 8; w++) { mn = fminf(mn, smn[w]); mx = fmaxf(mx, smx[w]); }
        atomicMin(&g_xmn[bc], fenc(mn));
        atomicMax(&g_xmx[bc], fenc(mx));
    }
}

// level = output pyramid level (1..8). Input is x (normalized on the fly)
// for level==1, otherwise stored level-1.
__global__ void k_pyrdown(const float* __restrict__ x, int level) {
    int ho = 256 >> (level - 1);
    int hi = ho * 2;
    int per = ho * ho;
    int t = blockIdx.x * blockDim.x + threadIdx.x;
    if (t >= BC * per) return;
    int bc = t / per;
    int r = t - bc * per;
    int oy = r / ho, ox = r - (r / ho) * ho;

    const float* in;
    float a = 1.f, b0 = 0.f;
    if (level == 1) {
        in = x + (size_t)bc * 262144;
        float mn = fdec(g_xmn[bc]), mx = fdec(g_xmx[bc]);
        a = 1.f / (mx - mn);
        b0 = -mn * a;
    } else {
        in = g_pyr + c_off[level - 2] + (size_t)bc * hi * hi;
    }
    float* out = g_pyr + c_off[level - 1] + (size_t)bc * per;

    int iy[6], ix[6];
#pragma unroll
    for (int k = 0; k < 6; k++) {
        int ty = 2 * oy + k - 2;
        iy[k] = ty < 0 ? -ty : (ty >= hi ? 2 * hi - 2 - ty : ty);
        int tx = 2 * ox + k - 2;
        ix[k] = tx < 0 ? -tx : (tx >= hi ? 2 * hi - 2 - tx : tx);
    }
    const float w[6] = {0.03125f, 0.15625f, 0.3125f, 0.3125f, 0.15625f, 0.03125f};
    float acc = 0.f;
#pragma unroll
    for (int ry = 0; ry < 6; ry++) {
        const float* row = in + iy[ry] * hi;
        float rv = 0.f;
#pragma unroll
        for (int rx = 0; rx < 6; rx++) rv += w[rx] * row[ix[rx]];
        acc += w[ry] * rv;
    }
    out[oy * ho + ox] = a * acc + b0;  // affine commutes with the (sum=1) filter
}

// grid (tiles, tiles, 24), block 256 (16x16). Block == one 16x16 tile.
__global__ void k_diff(int i) {
    int h = 256 >> i;
    int hc = h >> 1;
    int bc = blockIdx.z;
    int tx = threadIdx.x & 15, ty = threadIdx.x >> 4;
    int gx = blockIdx.x * 16 + tx, gy = blockIdx.y * 16 + ty;

    const float* fine = g_pyr + c_off[i] + (size_t)bc * h * h;
    const float* coarse = g_pyr + c_off[i + 1] + (size_t)bc * hc * hc;
    float* dp = g_d + c_off[i] + (size_t)bc * h * h;

    float vmx = -CUDART_INF_F, vmn = CUDART_INF_F;
    if (gx < h && gy < h) {
        float d = fabsf(fine[gy * h + gx] - coarse[(gy >> 1) * hc + (gx >> 1)]);
        dp[gy * h + gx] = d;
        vmx = d; vmn = d;
    }
    for (int o = 16; o; o >>= 1) {
        vmx = fmaxf(vmx, __shfl_xor_sync(~0u, vmx, o));
        vmn = fminf(vmn, __shfl_xor_sync(~0u, vmn, o));
    }
    __shared__ float smx[8], smn[8];
    if ((threadIdx.x & 31) == 0) { smx[threadIdx.x >> 5] = vmx; smn[threadIdx.x >> 5] = vmn; }
    __syncthreads();
    if (threadIdx.x == 0) {
        for (int w = 1; w < 8; w++) { vmx = fmaxf(vmx, smx[w]); vmn = fminf(vmn, smn[w]); }
        atomicMax(&g_dmx[bc * 7 + i], fenc(vmx));
        atomicMin(&g_dmn[bc * 7 + i], fenc(vmn));
        int n = (h >> 4) - 1;  // torch loop skips the last tile row/col
        if (n > 0 && (int)blockIdx.x < n && (int)blockIdx.y < n)
            atomicAdd(&g_tsum[bc * 7 + i], vmx);
    }
}

// one block, 256 threads: 168 (bc,i) scalars -> s, off; off summed per batch
__global__ void k_scale() {
    __shared__ float soff[BC * 7];
    int t = threadIdx.x;
    if (t < BC * 7) {
        int i = t % 7;
        int h = 256 >> i;
        float mn = fdec(g_dmn[t]), mx = fdec(g_dmx[t]);
        float inv = 1.f / (mx - mn);
        int n = (h >> 4) - 1;
        float lm = (n > 0) ? (g_tsum[t] / (float)(n * n) - mn) * inv : 0.f;
        float om = 1.f - lm;
        float s = om * om * inv;
        g_s[t] = s;
        soff[t] = -mn * s;
    }
    __syncthreads();
    if (t < 8) {
        float o = 0.f;
        for (int j = 0; j < 21; j++) o += soff[t * 21 + j];
        g_offtot[t] = o;
    }
}

// fused: 7 bilinear upsamples x 3 channels x affine + channel mean
__global__ void k_final(float* __restrict__ out) {
    int t = blockIdx.x * blockDim.x + threadIdx.x;  // 8*512*512
    int b = t >> 18;
    int yx = t & 262143;
    int y = yx >> 9, x = yx & 511;
    float acc = 0.f;
#pragma unroll
    for (int i = 0; i < 7; i++) {
        int h = 256 >> i;
        float sc = (float)h * (1.0f / 512.0f);
        float fy = fminf(fmaxf((y + 0.5f) * sc - 0.5f, 0.f), (float)(h - 1));
        float fx = fminf(fmaxf((x + 0.5f) * sc - 0.5f, 0.f), (float)(h - 1));
        int y0 = (int)fy; float wy = fy - (float)y0;
        int x0 = (int)fx; float wx = fx - (float)x0;
        int y1 = min(y0 + 1, h - 1);
        int x1 = min(x0 + 1, h - 1);
        int base = c_off[i] + (b * 3) * h * h;
#pragma unroll
        for (int c = 0; c < 3; c++) {
            const float* dp = g_d + base + c * h * h;
            float v00 = dp[y0 * h + x0], v01 = dp[y0 * h + x1];
            float v10 = dp[y1 * h + x0], v11 = dp[y1 * h + x1];
            float v0 = v00 + wx * (v01 - v00);
            float v1 = v10 + wx * (v11 - v10);
            float v = v0 + wy * (v1 - v0);
            acc += v * g_s[(b * 3 + c) * 7 + i];
        }
    }
    out[t] = (acc + g_offtot[b]) * (1.f / 3.f);
}

extern "C" void kernel_launch(void* const* d_in, const int* in_sizes, int n_in,
                              void* d_out, int out_size) {
    const float* x = (const float*)d_in[0];
    float* out = (float*)d_out;

    k_init<<<1, 256>>>();
    k_minmax<<<dim3(24, 16), 256>>>(x);
    for (int lvl = 1; lvl <= 8; lvl++) {
        int ho = 256 >> (lvl - 1);
        int total = BC * ho * ho;
        k_pyrdown<<<(total + 255) / 256, 256>>>(x, lvl);
    }
    for (int i = 0; i < 7; i++) {
        int h = 256 >> i;
        int tiles = h >= 16 ? h / 16 : 1;
        k_diff<<<dim3(tiles, tiles, 24), 256>>>(i);
    }
    k_scale<<<1, 256>>>();
    k_final<<<(8 * 512 * 512) / 256, 256>>>(out);
}

// round 2
// speedup vs baseline: 1.2035x; 1.2035x over previous
#include <cuda_runtime.h>
#include <math_constants.h>

#define BC 24  // 8 batches * 3 channels

// ---------------------------------------------------------------------------
// IttiKochSaliency, x[8,3,512,512] -> out[8,512,512]
//
// Identity used: the whole pipeline is invariant under positive affine
// transforms of the input (linear sum-1 filters -> affine pyramids; diffs
// cancel the offset; per-map min-max normalization cancels the scale), so the
// reference's input normalization (and its 25MB min/max scan) is dropped.
//
// Launches (6 total):
//   k_pyr<0..2> : separable 6-tap [1,5,10,10,5,1]/32 stride-2 reflect filter
//                 via shared memory (== 5x5 binomial + bilinear half-resize)
//   k_mid       : blocks < 7680: diffs i=0,1 (16x16 tiles) with pair-dup
//                 float2 writes + per-tile min/max (no atomics);
//                 blocks >= 7680: per-(b,c) tail — pyramid 32..2 and diffs
//                 i=2..6 entirely in shared memory, stats written directly.
//   k_scale     : reduce tile stats -> per-(b,c,i) affine (s, off)
//   k_final     : fused 7-level x 3-channel bilinear gather using float2
//                 pair loads (1 LDG.64 per row sample), scales from smem.
// ---------------------------------------------------------------------------

__device__ float  g_pyr[2064384];   // levels k=0,1,2 (h=256,128,64) per bc
__device__ float2 g_e[2097024];     // pair-duplicated diff maps i=0..6
__device__ float  g_tmn[7680], g_tmx[7680];        // per-tile stats, i=0,1
__device__ float  g_mn2[168], g_mx2[168], g_ts2[168]; // direct stats, i=2..6
__device__ float  g_s[168];
__device__ float  g_off[8];

__device__ __constant__ int c_off[8] = {0, 1572864, 1966080, 2064384,
                                        2088960, 2095104, 2096640, 2097024};

__device__ __forceinline__ int refl(int t, int n) {
    return t < 0 ? -t : (t >= n ? 2 * n - 2 - t : t);
}

#define W0 0.03125f
#define W1 0.15625f
#define W2 0.3125f

// ---------------- separable pyrdown: HI -> HI/2, 32x8 output tile ----------
template <int LVL>
__global__ void __launch_bounds__(256) k_pyr(const float* __restrict__ x) {
    constexpr int HI = 512 >> LVL;
    constexpr int HO = HI / 2;
    __shared__ float s_in[20 * 68];
    __shared__ float s_h[20 * 32];
    const int bc = blockIdx.z;
    const int ox0 = blockIdx.x * 32, oy0 = blockIdx.y * 8;
    const float* in = (LVL == 0) ? (x + (size_t)bc * HI * HI)
                                 : (g_pyr + c_off[LVL - 1] + (size_t)bc * HI * HI);
    float* out = g_pyr + c_off[LVL] + (size_t)bc * HO * HO;
    const int t = threadIdx.x;
    const int iy0 = 2 * oy0 - 2, ix0 = 2 * ox0 - 2;
    for (int idx = t; idx < 20 * 68; idx += 256) {
        int r = idx / 68, c = idx - r * 68;
        s_in[idx] = in[refl(iy0 + r, HI) * HI + refl(ix0 + c, HI)];
    }
    __syncthreads();
    for (int idx = t; idx < 640; idx += 256) {
        int r = idx >> 5, c = idx & 31;
        const float* p = s_in + r * 68 + 2 * c;
        s_h[idx] = W0 * (p[0] + p[5]) + W1 * (p[1] + p[4]) + W2 * (p[2] + p[3]);
    }
    __syncthreads();
    const int tx = t & 31, ty = t >> 5;
    const float* q = s_h + 2 * ty * 32 + tx;
    float acc = W0 * (q[0] + q[160]) + W1 * (q[32] + q[128]) + W2 * (q[64] + q[96]);
    out[(oy0 + ty) * HO + ox0 + tx] = acc;
}

// ---------------- fused mid kernel ------------------------------------------
__global__ void __launch_bounds__(256) k_mid() {
    __shared__ float pool[4096 + 1024];
    __shared__ float wmn[8], wmx[8], stile[9];
    const int bx = blockIdx.x;
    const int t = threadIdx.x;

    if (bx < 7680) {
        // ---- diff i = 0 or 1, one 16x16 tile per block ----
        int i, bc, tile;
        if (bx < 6144) { i = 0; bc = bx >> 8; tile = bx & 255; }
        else           { i = 1; int r = bx - 6144; bc = r >> 6; tile = r & 63; }
        const int h = 256 >> i, hc = h >> 1, T = 16 >> i;
        const int tx0 = (tile % T) * 16, ty0 = (tile / T) * 16;
        const float* fine   = g_pyr + c_off[i]     + (size_t)bc * h * h;
        const float* coarse = g_pyr + c_off[i + 1] + (size_t)bc * hc * hc;
        float* sd = pool;  // [16][17]
        const int lx = t & 15, ly = t >> 4;
        const int gx = tx0 + lx, gy = ty0 + ly;
        float d = fabsf(fine[gy * h + gx] - coarse[(gy >> 1) * hc + (gx >> 1)]);
        sd[ly * 17 + lx] = d;
        if (lx == 0) {
            int gx2 = min(tx0 + 16, h - 1);
            sd[ly * 17 + 16] =
                fabsf(fine[gy * h + gx2] - coarse[(gy >> 1) * hc + (gx2 >> 1)]);
        }
        float vmn = d, vmx = d;
        for (int o = 16; o; o >>= 1) {
            vmn = fminf(vmn, __shfl_xor_sync(~0u, vmn, o));
            vmx = fmaxf(vmx, __shfl_xor_sync(~0u, vmx, o));
        }
        if ((t & 31) == 0) { wmn[t >> 5] = vmn; wmx[t >> 5] = vmx; }
        __syncthreads();
        float2* pe = g_e + c_off[i] + (size_t)bc * h * h;
        pe[gy * h + gx] = make_float2(sd[ly * 17 + lx], sd[ly * 17 + lx + 1]);
        if (t == 0) {
            float mn = wmn[0], mx = wmx[0];
            for (int w = 1; w < 8; w++) { mn = fminf(mn, wmn[w]); mx = fmaxf(mx, wmx[w]); }
            int idx = (i == 0 ? bc * 256 : 6144 + bc * 64) + tile;
            g_tmn[idx] = mn; g_tmx[idx] = mx;
        }
        return;
    }

    // ---- tail: per-(b,c) pyramid 32..2 + diffs i=2..6 in smem ----
    const int bc = bx - 7680;
    float* A = pool;
    float* B = pool + 4096;
    const float* src = g_pyr + c_off[2] + (size_t)bc * 4096;
    for (int idx = t; idx < 4096; idx += 256) A[idx] = src[idx];
    __syncthreads();
    float* F = A;
    float* C = B;
    int hf = 64;
    for (int s = 0; s < 5; s++, hf >>= 1) {
        const int hc = hf >> 1;
        // coarse level from F (reflect 6-tap, stride 2, both dims)
        for (int idx = t; idx < hc * hc; idx += 256) {
            int oy = idx / hc, ox = idx - oy * hc;
            float acc = 0.f;
#pragma unroll
            for (int ky = 0; ky < 6; ky++) {
                const float* row = F + refl(2 * oy - 2 + ky, hf) * hf;
                float rv = W0 * (row[refl(2 * ox - 2, hf)] + row[refl(2 * ox + 3, hf)])
                         + W1 * (row[refl(2 * ox - 1, hf)] + row[refl(2 * ox + 2, hf)])
                         + W2 * (row[2 * ox]               + row[refl(2 * ox + 1, hf)]);
                float wy = (ky == 0 || ky == 5) ? W0 : ((ky == 1 || ky == 4) ? W1 : W2);
                acc += wy * rv;
            }
            C[idx] = acc;
        }
        __syncthreads();
        // diff in-place into F
        for (int idx = t; idx < hf * hf; idx += 256) {
            int y = idx / hf;
            F[idx] = fabsf(F[idx] - C[(y >> 1) * hc + ((idx - y * hf) >> 1)]);
        }
        __syncthreads();
        // pair writes + stats
        const int i = s + 2;
        float2* pe = g_e + c_off[i] + (size_t)bc * hf * hf;
        float vmn = CUDART_INF_F, vmx = -CUDART_INF_F;
        for (int idx = t; idx < hf * hf; idx += 256) {
            int y = idx / hf, xx = idx - y * hf;
            float a0 = F[idx];
            float a1 = F[y * hf + min(xx + 1, hf - 1)];
            pe[idx] = make_float2(a0, a1);
            vmn = fminf(vmn, a0);
            vmx = fmaxf(vmx, a0);
        }
        for (int o = 16; o; o >>= 1) {
            vmn = fminf(vmn, __shfl_xor_sync(~0u, vmn, o));
            vmx = fmaxf(vmx, __shfl_xor_sync(~0u, vmx, o));
        }
        if ((t & 31) == 0) { wmn[t >> 5] = vmn; wmx[t >> 5] = vmx; }
        const int n = (hf >> 4) - 1;  // torch loop skips last tile row/col
        if (n > 0 && t < n * n) {
            int tj = t / n, ti = t - tj * n;
            float m = -CUDART_INF_F;
            for (int yy = 0; yy < 16; yy++)
                for (int xx2 = 0; xx2 < 16; xx2++)
                    m = fmaxf(m, F[(tj * 16 + yy) * hf + ti * 16 + xx2]);
            stile[t] = m;
        }
        __syncthreads();
        if (t == 0) {
            float mn = wmn[0], mx = wmx[0];
            for (int w = 1; w < 8; w++) { mn = fminf(mn, wmn[w]); mx = fmaxf(mx, wmx[w]); }
            float ts = 0.f;
            if (n > 0) for (int k2 = 0; k2 < n * n; k2++) ts += stile[k2];
            g_mn2[bc * 7 + i] = mn;
            g_mx2[bc * 7 + i] = mx;
            g_ts2[bc * 7 + i] = ts;
        }
        __syncthreads();
        float* tmp = F; F = C; C = tmp;
    }
}

// ---------------- reduce stats to affine coefficients -----------------------
__global__ void k_scale() {
    __shared__ float soff[168];
    const int t = threadIdx.x;
    if (t < 168) {
        const int i = t % 7;
        float mn, mx, ts = 0.f;
        int n;
        if (i < 2) {
            const int bc = t / 7;
            const int T = 16 >> i;
            const int base = (i == 0) ? bc * 256 : 6144 + bc * 64;
            n = T - 1;
            mn = CUDART_INF_F; mx = -CUDART_INF_F;
            for (int k = 0; k < T * T; k++) {
                mn = fminf(mn, g_tmn[base + k]);
                float m = g_tmx[base + k];
                mx = fmaxf(mx, m);
                int tj = k / T, ti = k - tj * T;
                if (ti < n && tj < n) ts += m;
            }
        } else {
            mn = g_mn2[t]; mx = g_mx2[t]; ts = g_ts2[t];
            n = ((256 >> i) >> 4) - 1;
        }
        float inv = 1.f / (mx - mn);
        float lm = (n > 0) ? (ts / (float)(n * n) - mn) * inv : 0.f;
        float om = 1.f - lm;
        float sc = om * om * inv;
        g_s[t] = sc;
        soff[t] = -mn * sc;
    }
    __syncthreads();
    if (t < 8) {
        float o = 0.f;
        for (int j = 0; j < 21; j++) o += soff[t * 21 + j];
        g_off[t] = o;
    }
}

// ---------------- fused final gather -----------------------------------------
__global__ void __launch_bounds__(256) k_final(float* __restrict__ out) {
    __shared__ float ss[168];
    __shared__ float sob;
    __shared__ int sr0[7], sr1[7];
    __shared__ float swy[7];
    const int t = threadIdx.x;
    const int b = blockIdx.x >> 10;             // 1024 blocks per batch
    const int y = (blockIdx.x & 1023) >> 1;     // 512 rows, 2 blocks/row
    const int x = ((blockIdx.x & 1) << 8) + t;
    if (t < 168) ss[t] = g_s[t];
    if (t == 255) sob = g_off[b];
    if (t >= 168 && t < 175) {
        int i = t - 168;
        int h = 256 >> i;
        float fy = fminf(fmaxf((y + 0.5f) * (float)h * (1.f / 512.f) - 0.5f, 0.f),
                         (float)(h - 1));
        int y0 = (int)fy;
        swy[i] = fy - (float)y0;
        sr0[i] = y0 * h;
        sr1[i] = min(y0 + 1, h - 1) * h;
    }
    __syncthreads();
    float acc = 0.f;
#pragma unroll
    for (int i = 0; i < 7; i++) {
        const int h = 256 >> i;
        float fx = fminf(fmaxf((x + 0.5f) * (float)h * (1.f / 512.f) - 0.5f, 0.f),
                         (float)(h - 1));
        int x0 = (int)fx;
        float wx = fx - (float)x0;
        float wy = swy[i];
        const float2* e0 = g_e + c_off[i] + (size_t)(b * 3) * h * h;
#pragma unroll
        for (int c = 0; c < 3; c++) {
            const float2* ep = e0 + (size_t)c * h * h;
            float2 p0 = ep[sr0[i] + x0];
            float2 p1 = ep[sr1[i] + x0];
            float v0 = fmaf(wx, p0.y - p0.x, p0.x);
            float v1 = fmaf(wx, p1.y - p1.x, p1.x);
            float v = fmaf(wy, v1 - v0, v0);
            acc = fmaf(v, ss[(b * 3 + c) * 7 + i], acc);
        }
    }
    out[((size_t)b << 18) + y * 512 + x] = (acc + sob) * (1.f / 3.f);
}

extern "C" void kernel_launch(void* const* d_in, const int* in_sizes, int n_in,
                              void* d_out, int out_size) {
    const float* x = (const float*)d_in[0];
    float* out = (float*)d_out;

    k_pyr<0><<<dim3(8, 32, 24), 256>>>(x);   // 512 -> 256
    k_pyr<1><<<dim3(4, 16, 24), 256>>>(x);   // 256 -> 128
    k_pyr<2><<<dim3(2, 8, 24), 256>>>(x);    // 128 -> 64
    k_mid<<<7704, 256>>>();                  // diffs i=0,1 + tail pyramid/diffs
    k_scale<<<1, 192>>>();
    k_final<<<8192, 256>>>(out);
}

// round 3
// speedup vs baseline: 1.7756x; 1.4754x over previous
#include <cuda_runtime.h>
#include <math_constants.h>

// ---------------------------------------------------------------------------
// IttiKochSaliency, x[8,3,512,512] -> out[8,512,512]
//
// Identities used:
//  * pipeline is invariant under positive affine input transforms -> the
//    reference's input normalization is dropped entirely.
//  * bilinear resize and channel-mean are linear -> the 3 channels are
//    pre-combined (scaled) into ONE float2 pair-dup map per (b,level), so the
//    final gather needs only 14 LDG.64 per pixel.
//
// Launch sequence (7):
//  k_pyr<0..2> : separable 6-tap [1,5,10,10,5,1]/32 stride-2 reflect filter
//                (== 5x5 binomial + bilinear half-resize); block(0,0,0) of
//                k_pyr<0> also resets the stat counters.
//  k_mid       : blocks <24 FIRST: per-(b,c) tail — pyramid 64->2 + diffs
//                i=2..6 fully in smem (separable), stats stored directly;
//                blocks >=24: diffs i=0,1 as 16x16 tiles, stats via atomics.
//  k_scale     : stats -> per-(b,c,i) affine (s/3, off/3 summed per batch)
//  k_comb      : per (b,i): combined = sum_c s_bc * d_bc, pair-dup float2
//  k_final     : 7-level bilinear gather, 2 LDG.64 per level per pixel.
// ---------------------------------------------------------------------------

__device__ float    g_pyr[2064384];   // pyr levels 0..2 (h=256,128,64) per bc
__device__ float    g_d[2097024];     // diff maps i=0..6 per bc
__device__ float2   g_comb[699008];   // combined scaled maps per (b,i)
__device__ unsigned g_dmn[168], g_dmx[168];
__device__ float    g_tsum[168];
__device__ float    g_s[168];
__device__ float    g_off[8];

__constant__ int c_off[8] = {0, 1572864, 1966080, 2064384,
                             2088960, 2095104, 2096640, 2097024};
__constant__ int co2[8]  = {0, 524288, 655360, 688128,
                            696320, 698368, 698880, 699008};
__constant__ int cblk[7] = {0, 2048, 2560, 2688, 2720, 2728, 2730};

__device__ __forceinline__ int refl(int t, int n) {
    return t < 0 ? -t : (t >= n ? 2 * n - 2 - t : t);
}
__device__ __forceinline__ unsigned fenc(float f) {
    unsigned u = __float_as_uint(f);
    return (u & 0x80000000u) ? ~u : (u | 0x80000000u);
}
__device__ __forceinline__ float fdec(unsigned u) {
    return __uint_as_float((u & 0x80000000u) ? (u ^ 0x80000000u) : ~u);
}

#define W0 0.03125f
#define W1 0.15625f
#define W2 0.3125f

// ---------------- separable pyrdown: HI -> HI/2, 32x8 output tile -----------
template <int LVL>
__global__ void __launch_bounds__(256) k_pyr(const float* __restrict__ x) {
    constexpr int HI = 512 >> LVL;
    constexpr int HO = HI / 2;
    __shared__ float s_in[20 * 68];
    __shared__ float s_h[20 * 32];
    const int t = threadIdx.x;
    if (LVL == 0 && blockIdx.x == 0 && blockIdx.y == 0 && blockIdx.z == 0) {
        if (t < 168) { g_dmn[t] = 0xFFFFFFFFu; g_dmx[t] = 0u; g_tsum[t] = 0.f; }
    }
    const int bc = blockIdx.z;
    const int ox0 = blockIdx.x * 32, oy0 = blockIdx.y * 8;
    const float* in = (LVL == 0) ? (x + (size_t)bc * HI * HI)
                                 : (g_pyr + c_off[LVL - 1] + (size_t)bc * HI * HI);
    float* out = g_pyr + c_off[LVL] + (size_t)bc * HO * HO;
    const int iy0 = 2 * oy0 - 2, ix0 = 2 * ox0 - 2;
    for (int idx = t; idx < 20 * 68; idx += 256) {
        int r = idx / 68, c = idx - r * 68;
        s_in[idx] = in[refl(iy0 + r, HI) * HI + refl(ix0 + c, HI)];
    }
    __syncthreads();
    for (int idx = t; idx < 640; idx += 256) {
        int r = idx >> 5, c = idx & 31;
        const float* p = s_in + r * 68 + 2 * c;
        s_h[idx] = W0 * (p[0] + p[5]) + W1 * (p[1] + p[4]) + W2 * (p[2] + p[3]);
    }
    __syncthreads();
    const int tx = t & 31, ty = t >> 5;
    const float* q = s_h + 2 * ty * 32 + tx;
    float acc = W0 * (q[0] + q[160]) + W1 * (q[32] + q[128]) + W2 * (q[64] + q[96]);
    out[(oy0 + ty) * HO + ox0 + tx] = acc;
}

// ---------------- fused mid kernel -------------------------------------------
__global__ void __launch_bounds__(256) k_mid() {
    __shared__ float A[4096];
    __shared__ float Hs[2048];
    __shared__ float Bb[1024];
    __shared__ float wmn[8], wmx[8], wt[8], stile[9];
    const int bx = blockIdx.x;
    const int t = threadIdx.x;

    if (bx >= 24) {
        // ---- diff i = 0 or 1, one 16x16 tile per block ----
        int bx2 = bx - 24;
        int i, bc, tile;
        if (bx2 < 6144) { i = 0; bc = bx2 >> 8; tile = bx2 & 255; }
        else { bx2 -= 6144; i = 1; bc = bx2 >> 6; tile = bx2 & 63; }
        const int h = 256 >> i, hc = h >> 1, T = 16 >> i;
        const int ti = tile & (T - 1), tj = tile >> (4 - i);
        const int gx = ti * 16 + (t & 15), gy = tj * 16 + (t >> 4);
        const float* fine   = g_pyr + c_off[i]     + (size_t)bc * h * h;
        const float* coarse = g_pyr + c_off[i + 1] + (size_t)bc * hc * hc;
        float d = fabsf(fine[gy * h + gx] - coarse[(gy >> 1) * hc + (gx >> 1)]);
        g_d[c_off[i] + (size_t)bc * h * h + gy * h + gx] = d;
        float vmn = d, vmx = d;
        for (int o = 16; o; o >>= 1) {
            vmn = fminf(vmn, __shfl_xor_sync(~0u, vmn, o));
            vmx = fmaxf(vmx, __shfl_xor_sync(~0u, vmx, o));
        }
        if ((t & 31) == 0) { wmn[t >> 5] = vmn; wmx[t >> 5] = vmx; }
        __syncthreads();
        if (t == 0) {
            float mn = wmn[0], mx = wmx[0];
            for (int w = 1; w < 8; w++) { mn = fminf(mn, wmn[w]); mx = fmaxf(mx, wmx[w]); }
            atomicMin(&g_dmn[bc * 7 + i], fenc(mn));
            atomicMax(&g_dmx[bc * 7 + i], fenc(mx));
            int n = T - 1;  // torch loop skips last tile row/col
            if (ti < n && tj < n) atomicAdd(&g_tsum[bc * 7 + i], mx);
        }
        return;
    }

    // ---- tail: per-(b,c) pyramid 64..2 + diffs i=2..6 in smem ----
    const int bc = bx;
    const float* src = g_pyr + c_off[2] + (size_t)bc * 4096;
    for (int idx = t; idx < 4096; idx += 256) A[idx] = src[idx];
    __syncthreads();
    float* F = A;
    float* C = Bb;
    int lgf = 6;
    for (int s = 0; s < 5; s++, lgf--) {
        const int hf = 1 << lgf, hc = hf >> 1;
        // horizontal stride-2 pass: F[hf][hf] -> Hs[hf][hc]
        for (int idx = t; idx < hf * hc; idx += 256) {
            int r = idx >> (lgf - 1), c = idx & (hc - 1);
            const float* row = F + (r << lgf);
            Hs[idx] = W0 * (row[refl(2 * c - 2, hf)] + row[refl(2 * c + 3, hf)])
                    + W1 * (row[refl(2 * c - 1, hf)] + row[refl(2 * c + 2, hf)])
                    + W2 * (row[2 * c] + row[2 * c + 1]);
        }
        __syncthreads();
        // vertical stride-2 pass: Hs -> C[hc][hc]
        for (int idx = t; idx < hc * hc; idx += 256) {
            int oy = idx >> (lgf - 1), ox = idx & (hc - 1);
            float acc = 0.f;
#pragma unroll
            for (int ky = 0; ky < 6; ky++) {
                float wv = (ky == 0 || ky == 5) ? W0 : ((ky == 1 || ky == 4) ? W1 : W2);
                acc += wv * Hs[(refl(2 * oy - 2 + ky, hf) << (lgf - 1)) + ox];
            }
            C[idx] = acc;
        }
        __syncthreads();
        // diff in place
        for (int idx = t; idx < hf * hf; idx += 256) {
            int yy = idx >> lgf, xx = idx & (hf - 1);
            F[idx] = fabsf(F[idx] - C[((yy >> 1) << (lgf - 1)) + (xx >> 1)]);
        }
        __syncthreads();
        // write + stats
        const int i = s + 2;
        float* gd = g_d + c_off[i] + (size_t)bc * hf * hf;
        float vmn = CUDART_INF_F, vmx = -CUDART_INF_F;
        for (int idx = t; idx < hf * hf; idx += 256) {
            float a = F[idx];
            gd[idx] = a;
            vmn = fminf(vmn, a);
            vmx = fmaxf(vmx, a);
        }
        for (int o = 16; o; o >>= 1) {
            vmn = fminf(vmn, __shfl_xor_sync(~0u, vmn, o));
            vmx = fmaxf(vmx, __shfl_xor_sync(~0u, vmx, o));
        }
        if ((t & 31) == 0) { wmn[t >> 5] = vmn; wmx[t >> 5] = vmx; }
        if (lgf == 6) {
            // 3x3 tiles of 16x16: 16 lanes per tile (tiles 9..15 dummy)
            int tile = t >> 4, l = t & 15;
            int tt = tile < 9 ? tile : 0;
            int tix = tt % 3, tjy = tt / 3;
            float m = -CUDART_INF_F;
#pragma unroll
            for (int rr = 0; rr < 16; rr++)
                m = fmaxf(m, F[(tjy * 16 + rr) * 64 + tix * 16 + l]);
            for (int o = 8; o; o >>= 1) m = fmaxf(m, __shfl_xor_sync(~0u, m, o, 16));
            if (l == 0 && tile < 9) stile[tile] = m;
        } else if (lgf == 5) {
            // single 16x16 tile (top-left of 32x32)
            float m = F[(t >> 4) * 32 + (t & 15)];
            for (int o = 16; o; o >>= 1) m = fmaxf(m, __shfl_xor_sync(~0u, m, o));
            if ((t & 31) == 0) wt[t >> 5] = m;
        }
        __syncthreads();
        if (t == 0) {
            float mn = wmn[0], mx = wmx[0];
            for (int w = 1; w < 8; w++) { mn = fminf(mn, wmn[w]); mx = fmaxf(mx, wmx[w]); }
            float ts = 0.f;
            if (lgf == 6) for (int k = 0; k < 9; k++) ts += stile[k];
            else if (lgf == 5) { ts = wt[0]; for (int w = 1; w < 8; w++) ts = fmaxf(ts, wt[w]); }
            g_dmn[bc * 7 + i] = fenc(mn);
            g_dmx[bc * 7 + i] = fenc(mx);
            g_tsum[bc * 7 + i] = ts;
        }
        __syncthreads();
        float* tmp = F; F = C; C = tmp;
    }
}

// ---------------- stats -> affine coefficients --------------------------------
__global__ void k_scale() {
    __shared__ float soff[168];
    const int t = threadIdx.x;
    if (t < 168) {
        const int i = t % 7;
        float mn = fdec(g_dmn[t]), mx = fdec(g_dmx[t]);
        float ts = g_tsum[t];
        int n = (16 >> i) - 1;
        float inv = 1.f / (mx - mn);
        float lm = (n > 0) ? (ts / (float)(n * n) - mn) * inv : 0.f;
        float om = 1.f - lm;
        float sc = om * om * inv * (1.f / 3.f);
        g_s[t] = sc;
        soff[t] = -mn * sc;
    }
    __syncthreads();
    if (t < 8) {
        float o = 0.f;
        for (int j = 0; j < 21; j++) o += soff[t * 21 + j];
        g_off[t] = o;
    }
}

// ---------------- combine 3 channels into scaled pair-dup float2 --------------
__global__ void __launch_bounds__(256) k_comb() {
    const int bx = blockIdx.x;
    int i = 0;
#pragma unroll
    for (int k = 1; k < 7; k++) if (bx >= cblk[k]) i = k;
    const int lg = 8 - i;
    const int hh = 1 << (2 * lg);
    const int idx = ((bx - cblk[i]) << 8) + threadIdx.x;
    if (idx >= (hh << 3)) return;
    const int b = idx >> (2 * lg);
    const int r = idx & (hh - 1);
    const int y = r >> lg, x = r & ((1 << lg) - 1);
    const int x1 = min(x + 1, (1 << lg) - 1);
    const float* dp = g_d + c_off[i] + (size_t)(b * 3) * hh;
    const float* sp = g_s + b * 21 + i;
    float v0 = 0.f, v1 = 0.f;
#pragma unroll
    for (int c = 0; c < 3; c++) {
        float sc = sp[c * 7];
        v0 = fmaf(dp[r], sc, v0);
        v1 = fmaf(dp[(y << lg) + x1], sc, v1);
        dp += hh;
    }
    g_comb[co2[i] + b * hh + r] = make_float2(v0, v1);
}

// ---------------- fused final gather ------------------------------------------
__global__ void __launch_bounds__(256) k_final(float* __restrict__ out) {
    __shared__ int sr0[7], sr1[7];
    __shared__ float swy[7];
    __shared__ float sob;
    const int t = threadIdx.x;
    const int b = blockIdx.x >> 10;
    const int y = (blockIdx.x & 1023) >> 1;
    const int x = ((blockIdx.x & 1) << 8) + t;
    if (t < 7) {
        int h = 256 >> t;
        float fy = fminf(fmaxf((y + 0.5f) * (float)h * (1.f / 512.f) - 0.5f, 0.f),
                         (float)(h - 1));
        int y0 = (int)fy;
        swy[t] = fy - (float)y0;
        sr0[t] = y0 * h;
        sr1[t] = min(y0 + 1, h - 1) * h;
    }
    if (t == 32) sob = g_off[b];
    __syncthreads();
    float acc = 0.f;
#pragma unroll
    for (int i = 0; i < 7; i++) {
        const int h = 256 >> i;
        float fx = fminf(fmaxf((x + 0.5f) * (float)h * (1.f / 512.f) - 0.5f, 0.f),
                         (float)(h - 1));
        int x0 = (int)fx;
        float wx = fx - (float)x0;
        const float2* ep = g_comb + co2[i] + b * h * h;
        float2 p0 = ep[sr0[i] + x0];
        float2 p1 = ep[sr1[i] + x0];
        float v0 = fmaf(wx, p0.y - p0.x, p0.x);
        float v1 = fmaf(wx, p1.y - p1.x, p1.x);
        acc += fmaf(swy[i], v1 - v0, v0);
    }
    out[((size_t)b << 18) + y * 512 + x] = acc + sob;
}

extern "C" void kernel_launch(void* const* d_in, const int* in_sizes, int n_in,
                              void* d_out, int out_size) {
    const float* x = (const float*)d_in[0];
    float* out = (float*)d_out;

    k_pyr<0><<<dim3(8, 32, 24), 256>>>(x);   // 512 -> 256 (+ stat init)
    k_pyr<1><<<dim3(4, 16, 24), 256>>>(x);   // 256 -> 128
    k_pyr<2><<<dim3(2, 8, 24), 256>>>(x);    // 128 -> 64
    k_mid<<<7704, 256>>>();                  // tail first, then diffs i=0,1
    k_scale<<<1, 192>>>();
    k_comb<<<2731, 256>>>();
    k_final<<<8192, 256>>>(out);
}